// round 2
// baseline (speedup 1.0000x reference)
#include <cuda_runtime.h>
#include <cstdint>

#define SEQ   2048
#define EMB   768
#define NH    12
#define HD    64
#define BATCH 2
#define MROWS (BATCH * SEQ)   // 4096

typedef unsigned long long ull;

// ---------------- f32x2 helpers (FFMA2 path: only reachable via PTX) --------
__device__ __forceinline__ ull splat2(float x) {
    ull r;
    asm("mov.b64 %0, {%1, %1};" : "=l"(r) : "r"(__float_as_uint(x)));
    return r;
}
__device__ __forceinline__ void fma2(ull& d, ull a, ull b) {
    asm("fma.rn.f32x2 %0, %1, %2, %0;" : "+l"(d) : "l"(a), "l"(b));
}
__device__ __forceinline__ void mul2(ull& d, ull a) {
    asm("mul.rn.f32x2 %0, %0, %1;" : "+l"(d) : "l"(a));
}
__device__ __forceinline__ float hadd2(ull v) {
    float2 f = *(float2*)&v;
    return f.x + f.y;
}
__device__ __forceinline__ float ex2f(float x) {
    float y;
    asm("ex2.approx.ftz.f32 %0, %1;" : "=f"(y) : "f"(x));
    return y;
}

// ---------------- scratch (static device arrays; no allocation) -------------
__device__ float g_q[BATCH * NH * SEQ * HD];   // [b*NH+h][n][d]  (log2e folded)
__device__ float g_k[BATCH * NH * SEQ * HD];
__device__ float g_v[BATCH * NH * SEQ * HD];
__device__ float g_ao[BATCH * SEQ * EMB];      // attention output, [b][n][emb]

// =================================================================
// GEMM: C = (A @ W^T + bias) * scale   (FFMA2 inner loop)
// =================================================================
#define GBM 128
#define GBN 128
#define GBK 16
#define GST (GBM + 4)   // 132 floats; row stride 528B (16B aligned)

__device__ __forceinline__ void gemm_tile_body(
    const float* __restrict__ A, const float* __restrict__ W,
    const float* __restrict__ bias, float* __restrict__ C,
    int m0, int n0, float scale, int remap)
{
    __shared__ float As[GBK][GST];
    __shared__ float Bs[GBK][GST];

    const int tid = threadIdx.x;
    const int ty = tid >> 4, tx = tid & 15;

    ull acc2[8][4];   // j packed in pairs: acc2[i][j] = (col 2j, col 2j+1)
#pragma unroll
    for (int i = 0; i < 8; i++)
#pragma unroll
        for (int j = 0; j < 4; j++) acc2[i][j] = 0ull;

    for (int k0 = 0; k0 < EMB; k0 += GBK) {
#pragma unroll
        for (int it = 0; it < 2; it++) {
            int e = it * 256 + tid;
            int row = e >> 2;
            int c4 = (e & 3) * 4;
            float4 va = *(const float4*)&A[(size_t)(m0 + row) * EMB + k0 + c4];
            As[c4 + 0][row] = va.x; As[c4 + 1][row] = va.y;
            As[c4 + 2][row] = va.z; As[c4 + 3][row] = va.w;
            float4 vb = *(const float4*)&W[(size_t)(n0 + row) * EMB + k0 + c4];
            Bs[c4 + 0][row] = vb.x; Bs[c4 + 1][row] = vb.y;
            Bs[c4 + 2][row] = vb.z; Bs[c4 + 3][row] = vb.w;
        }
        __syncthreads();

#pragma unroll
        for (int k = 0; k < GBK; k++) {
            float a[8];
            *(float4*)&a[0] = *(const float4*)&As[k][ty * 8];
            *(float4*)&a[4] = *(const float4*)&As[k][ty * 8 + 4];
            ull b2[4];
            {
                ulonglong2 t0 = *(const ulonglong2*)&Bs[k][tx * 8];
                ulonglong2 t1 = *(const ulonglong2*)&Bs[k][tx * 8 + 4];
                b2[0] = t0.x; b2[1] = t0.y; b2[2] = t1.x; b2[3] = t1.y;
            }
#pragma unroll
            for (int i = 0; i < 8; i++) {
                ull av = splat2(a[i]);
#pragma unroll
                for (int j = 0; j < 4; j++) fma2(acc2[i][j], av, b2[j]);
            }
        }
        __syncthreads();
    }

    // epilogue
#pragma unroll
    for (int i = 0; i < 8; i++) {
        int m = m0 + ty * 8 + i;
        int b = m >> 11;
        int s = m & 2047;
#pragma unroll
        for (int j = 0; j < 4; j++) {
            float2 v = *(float2*)&acc2[i][j];
            int n = n0 + tx * 8 + 2 * j;
            float v0 = (v.x + bias[n]) * scale;
            float v1 = (v.y + bias[n + 1]) * scale;
            if (remap) {
                int h = n >> 6, d = n & 63;
                float* p = &C[(((size_t)(b * NH + h)) * SEQ + s) * HD + d];
                p[0] = v0; p[1] = v1;
            } else {
                float* p = &C[(size_t)m * EMB + n];
                p[0] = v0; p[1] = v1;
            }
        }
    }
}

__global__ __launch_bounds__(256) void qkv_gemm(
    const float* __restrict__ x,
    const float* __restrict__ wq, const float* __restrict__ bq,
    const float* __restrict__ wk, const float* __restrict__ bk,
    const float* __restrict__ wv, const float* __restrict__ bv)
{
    int m0 = blockIdx.y * GBM;
    int ng = blockIdx.x * GBN;
    int sel = ng / EMB;
    int n0 = ng - sel * EMB;

    const float* W = (sel == 0) ? wq : (sel == 1) ? wk : wv;
    const float* B = (sel == 0) ? bq : (sel == 1) ? bk : bv;
    float* C = (sel == 0) ? g_q : (sel == 1) ? g_k : g_v;
    // fold 1/sqrt(d) AND log2(e) into q so softmax can use raw ex2
    float scale = (sel == 0) ? 0.125f * 1.4426950408889634f : 1.0f;

    gemm_tile_body(x, W, B, C, m0, n0, scale, 1);
}

__global__ __launch_bounds__(256) void out_gemm(
    const float* __restrict__ A, const float* __restrict__ W,
    const float* __restrict__ bias, float* __restrict__ C)
{
    gemm_tile_body(A, W, bias, C, blockIdx.y * GBM, blockIdx.x * GBN, 1.0f, 0);
}

// =================================================================
// Flash attention (causal, online softmax, log2 domain).
// k-dim-packed FFMA2: Q,K natural (d-contiguous), V transposed
// (c-contiguous), P natural (c-contiguous). Zero splats in hot loops.
// =================================================================
#define ABM 64
#define ABN 64
#define AST 68   // 272B row stride, 16B aligned

__global__ __launch_bounds__(256) void attn_kernel(
    const float* __restrict__ Q, const float* __restrict__ K,
    const float* __restrict__ V, float* __restrict__ O)
{
    extern __shared__ float smem[];
    float (*Qs)[AST] = (float(*)[AST])(smem);                  // [ABM][d]
    float (*Ks)[AST] = (float(*)[AST])(smem + ABM * AST);      // [ABN][d]
    float (*Vt)[AST] = (float(*)[AST])(smem + 2 * ABM * AST);  // [d][c]
    float (*Ps)[AST] = (float(*)[AST])(smem + 3 * ABM * AST);  // [r][c]

    const int bh = blockIdx.y;
    const int qt = gridDim.x - 1 - (int)blockIdx.x;   // heavy tiles first
    const int qbase = qt * ABM;

    const float* Qb = Q + (size_t)bh * SEQ * HD;
    const float* Kb = K + (size_t)bh * SEQ * HD;
    const float* Vb = V + (size_t)bh * SEQ * HD;

    const int tid = threadIdx.x;
    const int tr = tid >> 4, tc = tid & 15;
    const int r0 = tr * 4, c0 = tc * 4;

    // Q natural: straight float4 copy (coalesced, no transpose)
#pragma unroll
    for (int it = 0; it < 4; it++) {
        int e = it * 256 + tid;
        int n = e >> 4;
        int d4 = (e & 15) * 4;
        *(float4*)&Qs[n][d4] = *(const float4*)&Qb[(size_t)(qbase + n) * HD + d4];
    }

    float m_i[4], l_i[4];
    ull o2[4][4];   // packed over c (reduction); j = output d col
#pragma unroll
    for (int i = 0; i < 4; i++) {
        m_i[i] = -1e30f;
        l_i[i] = 0.f;
#pragma unroll
        for (int j = 0; j < 4; j++) o2[i][j] = 0ull;
    }

    for (int kt = 0; kt <= qt; kt++) {
        const int kbase = kt * ABN;
        __syncthreads();   // previous tile's PV reads done

        // K natural + V transposed
#pragma unroll
        for (int it = 0; it < 4; it++) {
            int e = it * 256 + tid;
            int n = e >> 4;
            int d4 = (e & 15) * 4;
            *(float4*)&Ks[n][d4] = *(const float4*)&Kb[(size_t)(kbase + n) * HD + d4];
            int d4v = (e >> 6) * 4;
            int nv = e & 63;
            float4 vv = *(const float4*)&Vb[(size_t)(kbase + nv) * HD + d4v];
            Vt[d4v + 0][nv] = vv.x; Vt[d4v + 1][nv] = vv.y;
            Vt[d4v + 2][nv] = vv.z; Vt[d4v + 3][nv] = vv.w;
        }
        __syncthreads();

        // ---- S = Q K^T, packed over d ----
        ull s2[4][4];
#pragma unroll
        for (int i = 0; i < 4; i++)
#pragma unroll
            for (int j = 0; j < 4; j++) s2[i][j] = 0ull;

#pragma unroll
        for (int d4 = 0; d4 < HD; d4 += 4) {
            ull qa[4][2], kb[4][2];
#pragma unroll
            for (int i = 0; i < 4; i++) {
                ulonglong2 t = *(const ulonglong2*)&Qs[r0 + i][d4];
                qa[i][0] = t.x; qa[i][1] = t.y;
            }
#pragma unroll
            for (int j = 0; j < 4; j++) {
                ulonglong2 t = *(const ulonglong2*)&Ks[c0 + j][d4];
                kb[j][0] = t.x; kb[j][1] = t.y;
            }
#pragma unroll
            for (int i = 0; i < 4; i++)
#pragma unroll
                for (int j = 0; j < 4; j++) {
                    fma2(s2[i][j], qa[i][0], kb[j][0]);
                    fma2(s2[i][j], qa[i][1], kb[j][1]);
                }
        }

        float s[4][4];
#pragma unroll
        for (int i = 0; i < 4; i++)
#pragma unroll
            for (int j = 0; j < 4; j++) s[i][j] = hadd2(s2[i][j]);

        if (kt == qt) {
#pragma unroll
            for (int i = 0; i < 4; i++)
#pragma unroll
                for (int j = 0; j < 4; j++)
                    if (c0 + j > r0 + i) s[i][j] = -1e30f;
        }

        // ---- online softmax (log2 domain: logits already × log2e) ----
#pragma unroll
        for (int i = 0; i < 4; i++) {
            float rm = fmaxf(fmaxf(s[i][0], s[i][1]), fmaxf(s[i][2], s[i][3]));
#pragma unroll
            for (int off = 1; off < 16; off <<= 1)
                rm = fmaxf(rm, __shfl_xor_sync(0xffffffffu, rm, off));
            float mn = fmaxf(m_i[i], rm);
            float corr = ex2f(m_i[i] - mn);
            m_i[i] = mn;
            float rs = 0.f;
#pragma unroll
            for (int j = 0; j < 4; j++) {
                s[i][j] = ex2f(s[i][j] - mn);
                rs += s[i][j];
            }
#pragma unroll
            for (int off = 1; off < 16; off <<= 1)
                rs += __shfl_xor_sync(0xffffffffu, rs, off);
            l_i[i] = l_i[i] * corr + rs;
            ull c2 = splat2(corr);
#pragma unroll
            for (int j = 0; j < 4; j++) mul2(o2[i][j], c2);
        }

#pragma unroll
        for (int i = 0; i < 4; i++)
            *(float4*)&Ps[r0 + i][c0] = make_float4(s[i][0], s[i][1], s[i][2], s[i][3]);
        __syncthreads();

        // ---- O += P @ V, packed over c ----
#pragma unroll
        for (int cc = 0; cc < ABN; cc += 4) {
            ull pa[4][2], vb[4][2];
#pragma unroll
            for (int i = 0; i < 4; i++) {
                ulonglong2 t = *(const ulonglong2*)&Ps[r0 + i][cc];
                pa[i][0] = t.x; pa[i][1] = t.y;
            }
#pragma unroll
            for (int j = 0; j < 4; j++) {
                ulonglong2 t = *(const ulonglong2*)&Vt[c0 + j][cc];
                vb[j][0] = t.x; vb[j][1] = t.y;
            }
#pragma unroll
            for (int i = 0; i < 4; i++)
#pragma unroll
                for (int j = 0; j < 4; j++) {
                    fma2(o2[i][j], pa[i][0], vb[j][0]);
                    fma2(o2[i][j], pa[i][1], vb[j][1]);
                }
        }
    }

    // epilogue -> [b, n, emb]
    const int b = bh / NH, h = bh % NH;
#pragma unroll
    for (int i = 0; i < 4; i++) {
        float inv = 1.f / l_i[i];
        int n = qbase + r0 + i;
        float* op = O + ((size_t)b * SEQ + n) * EMB + h * HD + c0;
        *(float4*)op = make_float4(hadd2(o2[i][0]) * inv, hadd2(o2[i][1]) * inv,
                                   hadd2(o2[i][2]) * inv, hadd2(o2[i][3]) * inv);
    }
}

// =================================================================
// launch
// =================================================================
extern "C" void kernel_launch(void* const* d_in, const int* in_sizes, int n_in,
                              void* d_out, int out_size)
{
    const float* x    = (const float*)d_in[0];
    const float* wq_w = (const float*)d_in[1];
    const float* wq_b = (const float*)d_in[2];
    const float* wk_w = (const float*)d_in[3];
    const float* wk_b = (const float*)d_in[4];
    const float* wv_w = (const float*)d_in[5];
    const float* wv_b = (const float*)d_in[6];
    const float* wo_w = (const float*)d_in[7];
    const float* wo_b = (const float*)d_in[8];
    float* out = (float*)d_out;

    float *q, *k, *v, *ao;
    cudaGetSymbolAddress((void**)&q, g_q);
    cudaGetSymbolAddress((void**)&k, g_k);
    cudaGetSymbolAddress((void**)&v, g_v);
    cudaGetSymbolAddress((void**)&ao, g_ao);

    const int attn_smem = 4 * ABM * AST * (int)sizeof(float);   // ~68 KB
    cudaFuncSetAttribute(attn_kernel,
                         cudaFuncAttributeMaxDynamicSharedMemorySize, attn_smem);

    dim3 gqkv(3 * EMB / GBN, MROWS / GBM);      // 18 x 32 = 576 blocks
    qkv_gemm<<<gqkv, 256>>>(x, wq_w, wq_b, wk_w, wk_b, wv_w, wv_b);

    dim3 ga(SEQ / ABM, BATCH * NH);             // 32 x 24
    attn_kernel<<<ga, 256, attn_smem>>>(q, k, v, ao);

    dim3 go(EMB / GBN, MROWS / GBM);            // 6 x 32
    out_gemm<<<go, 256>>>(ao, wo_w, wo_b, out);
}

// round 3
// speedup vs baseline: 2.0344x; 2.0344x over previous
#include <cuda_runtime.h>
#include <cuda_bf16.h>
#include <cstdint>

#define SEQ   2048
#define EMB   768
#define NH    12
#define HD    64
#define BATCH 2
#define MROWS (BATCH * SEQ)   // 4096
#define NQKV  (3 * EMB)       // 2304

typedef __nv_bfloat16 bf16;

// ---------------- scratch (static device arrays; no allocation) -------------
__device__ bf16  g_xhi[MROWS * EMB], g_xlo[MROWS * EMB];
__device__ bf16  g_whi[4][EMB * EMB], g_wlo[4][EMB * EMB];   // q,k,v,o
__device__ bf16  g_aohi[MROWS * EMB], g_aolo[MROWS * EMB];
__device__ float g_q[BATCH * NH * SEQ * HD];   // [b*NH+h][n][d], scaled 1/8
__device__ float g_k[BATCH * NH * SEQ * HD];
__device__ float g_v[BATCH * NH * SEQ * HD];
__device__ float g_ao[BATCH * SEQ * EMB];      // attention output [b][n][emb]

// =================================================================
// fp32 -> bf16 hi/lo split conversion
// =================================================================
__global__ __launch_bounds__(256) void split_kernel(
    const float* __restrict__ src, bf16* __restrict__ hi,
    bf16* __restrict__ lo, int n)
{
    int i = blockIdx.x * 256 + threadIdx.x;
    if (i < n) {
        float v = src[i];
        bf16 h = __float2bfloat16(v);
        hi[i] = h;
        lo[i] = __float2bfloat16(v - __bfloat162float(h));
    }
}

__global__ __launch_bounds__(256) void split_w_kernel(
    const float* __restrict__ wq, const float* __restrict__ wk,
    const float* __restrict__ wv, const float* __restrict__ wo)
{
    int z = blockIdx.z;
    const float* src = (z == 0) ? wq : (z == 1) ? wk : (z == 2) ? wv : wo;
    bf16* hi = g_whi[z];
    bf16* lo = g_wlo[z];
    int i = blockIdx.x * 256 + threadIdx.x;
    if (i < EMB * EMB) {
        float v = src[i];
        bf16 h = __float2bfloat16(v);
        hi[i] = h;
        lo[i] = __float2bfloat16(v - __bfloat162float(h));
    }
}

// =================================================================
// bf16-split MMA GEMM:  C = (A @ W^T + bias) * scale
//   A = Ahi + Alo (fp32 split), W = Whi + Wlo.
//   C ≈ Ahi·Whi + Ahi·Wlo + Alo·Whi   (3 K-passes, fp32 accum)
// Tiles: BM=128, BN=128, BK=32. 8 warps (2m x 4n), warp tile 64x32.
// =================================================================
#define BM 128
#define BN 128
#define BK 32
#define LDSK 40          // padded row stride in bf16 elems (80B: 5 mod 8 -> ldmatrix conflict-free)
#define NKB (EMB / BK)   // 24
#define NIT (3 * NKB)    // 72
#define BUF_ELEMS (BM * LDSK)

__device__ __forceinline__ void ldsm4(uint32_t& r0, uint32_t& r1,
                                      uint32_t& r2, uint32_t& r3, uint32_t addr)
{
    asm volatile("ldmatrix.sync.aligned.m8n8.x4.shared.b16 {%0,%1,%2,%3}, [%4];"
                 : "=r"(r0), "=r"(r1), "=r"(r2), "=r"(r3) : "r"(addr));
}
__device__ __forceinline__ void mma16816(float c[4], const uint32_t a[4],
                                         uint32_t b0, uint32_t b1)
{
    asm volatile(
        "mma.sync.aligned.m16n8k16.row.col.f32.bf16.bf16.f32 "
        "{%0,%1,%2,%3}, {%4,%5,%6,%7}, {%8,%9}, {%0,%1,%2,%3};"
        : "+f"(c[0]), "+f"(c[1]), "+f"(c[2]), "+f"(c[3])
        : "r"(a[0]), "r"(a[1]), "r"(a[2]), "r"(a[3]), "r"(b0), "r"(b1));
}
__device__ __forceinline__ void cp16(uint32_t saddr, const void* gaddr)
{
    asm volatile("cp.async.cg.shared.global [%0], [%1], 16;"
                 :: "r"(saddr), "l"(gaddr));
}

template<int REMAP>
__device__ __forceinline__ void mma_gemm_body(
    const bf16* __restrict__ Ahi, const bf16* __restrict__ Alo,
    const bf16* __restrict__ Bhi, const bf16* __restrict__ Blo,
    const float* __restrict__ bias, float* __restrict__ C,
    int m0, int n0, float scale)
{
    __shared__ bf16 As[2][BUF_ELEMS];
    __shared__ bf16 Bs[2][BUF_ELEMS];

    const int tid = threadIdx.x;
    const int lane = tid & 31;
    const int wid = tid >> 5;
    const int wm = wid >> 2;       // 0..1
    const int wn = wid & 3;        // 0..3

    float acc[4][4][4];
#pragma unroll
    for (int i = 0; i < 4; i++)
#pragma unroll
        for (int j = 0; j < 4; j++)
#pragma unroll
            for (int t = 0; t < 4; t++) acc[i][j][t] = 0.f;

    // cp.async staging: 512 16B-chunks per tile, 2 per thread
    const int srow = tid >> 2;       // 0..63 (also +64)
    const int schk = (tid & 3) * 8;  // bf16 element offset of 16B chunk

    const uint32_t asb = (uint32_t)__cvta_generic_to_shared(&As[0][0]);
    const uint32_t bsb = (uint32_t)__cvta_generic_to_shared(&Bs[0][0]);

    // ldmatrix lane addressing (element offsets)
    const int laRow = wm * 64 + (lane & 15);
    const int laCol = (lane >> 4) * 8;
    const int lbRow = wn * 32 + ((lane >> 4) << 3) + (lane & 7);
    const int lbCol = ((lane >> 3) & 1) * 8;

    // ---- pipelined main loop over 3 splits x 24 k-blocks ----
#define ISSUE(IT, BUF)                                                        \
    do {                                                                      \
        int s_ = (IT) / NKB;                                                  \
        int k0_ = ((IT) - s_ * NKB) * BK;                                     \
        const bf16* Ap_ = (s_ == 2) ? Alo : Ahi;                              \
        const bf16* Bp_ = (s_ == 1) ? Blo : Bhi;                              \
        uint32_t sa_ = asb + (uint32_t)(BUF) * (BUF_ELEMS * 2);               \
        uint32_t sb_ = bsb + (uint32_t)(BUF) * (BUF_ELEMS * 2);               \
        cp16(sa_ + (srow * LDSK + schk) * 2,                                  \
             Ap_ + (size_t)(m0 + srow) * EMB + k0_ + schk);                   \
        cp16(sa_ + ((srow + 64) * LDSK + schk) * 2,                           \
             Ap_ + (size_t)(m0 + srow + 64) * EMB + k0_ + schk);              \
        cp16(sb_ + (srow * LDSK + schk) * 2,                                  \
             Bp_ + (size_t)(n0 + srow) * EMB + k0_ + schk);                   \
        cp16(sb_ + ((srow + 64) * LDSK + schk) * 2,                           \
             Bp_ + (size_t)(n0 + srow + 64) * EMB + k0_ + schk);              \
        asm volatile("cp.async.commit_group;");                               \
    } while (0)

    ISSUE(0, 0);

    for (int it = 0; it < NIT; it++) {
        const int buf = it & 1;
        if (it + 1 < NIT) {
            ISSUE(it + 1, buf ^ 1);
            asm volatile("cp.async.wait_group 1;");
        } else {
            asm volatile("cp.async.wait_group 0;");
        }
        __syncthreads();

        const uint32_t sa = asb + (uint32_t)buf * (BUF_ELEMS * 2);
        const uint32_t sb = bsb + (uint32_t)buf * (BUF_ELEMS * 2);

#pragma unroll
        for (int ks = 0; ks < 2; ks++) {
            uint32_t a[4][4];
#pragma unroll
            for (int mt = 0; mt < 4; mt++)
                ldsm4(a[mt][0], a[mt][1], a[mt][2], a[mt][3],
                      sa + (uint32_t)(((laRow + mt * 16) * LDSK) + ks * 16 + laCol) * 2);
            uint32_t b[2][4];
#pragma unroll
            for (int p = 0; p < 2; p++)
                ldsm4(b[p][0], b[p][1], b[p][2], b[p][3],
                      sb + (uint32_t)(((lbRow + p * 16) * LDSK) + ks * 16 + lbCol) * 2);
#pragma unroll
            for (int mt = 0; mt < 4; mt++) {
#pragma unroll
                for (int nt = 0; nt < 4; nt++)
                    mma16816(acc[mt][nt], a[mt],
                             b[nt >> 1][(nt & 1) * 2], b[nt >> 1][(nt & 1) * 2 + 1]);
            }
        }
        __syncthreads();
    }
#undef ISSUE

    // ---- epilogue ----
    const int er = lane >> 2;          // 0..7
    const int ec = (lane & 3) * 2;
#pragma unroll
    for (int mt = 0; mt < 4; mt++) {
        int m = m0 + wm * 64 + mt * 16 + er;   // and m+8
#pragma unroll
        for (int nt = 0; nt < 4; nt++) {
            int n = n0 + wn * 32 + nt * 8 + ec;
            float b0 = bias[n], b1 = bias[n + 1];
            float v00 = (acc[mt][nt][0] + b0) * scale;
            float v01 = (acc[mt][nt][1] + b1) * scale;
            float v10 = (acc[mt][nt][2] + b0) * scale;
            float v11 = (acc[mt][nt][3] + b1) * scale;
            if (REMAP) {
                int h = n >> 6, d = n & 63;
                int bb0 = m >> 11, s0 = m & 2047;
                int bb1 = (m + 8) >> 11, s1 = (m + 8) & 2047;
                float* p0 = &C[(((size_t)(bb0 * NH + h)) * SEQ + s0) * HD + d];
                float* p1 = &C[(((size_t)(bb1 * NH + h)) * SEQ + s1) * HD + d];
                *(float2*)p0 = make_float2(v00, v01);
                *(float2*)p1 = make_float2(v10, v11);
            } else {
                *(float2*)&C[(size_t)m * EMB + n] = make_float2(v00, v01);
                *(float2*)&C[(size_t)(m + 8) * EMB + n] = make_float2(v10, v11);
            }
        }
    }
}

__global__ __launch_bounds__(256, 2) void qkv_mma(
    const float* __restrict__ bq, const float* __restrict__ bk,
    const float* __restrict__ bv)
{
    int m0 = blockIdx.y * BM;
    int ng = blockIdx.x * BN;
    int sel = ng / EMB;                // block never straddles (768 % 128 == 0)
    int n0 = ng - sel * EMB;
    const bf16* Bhi = g_whi[sel];
    const bf16* Blo = g_wlo[sel];
    const float* bias = (sel == 0) ? bq : (sel == 1) ? bk : bv;
    float* C = (sel == 0) ? g_q : (sel == 1) ? g_k : g_v;
    float scale = (sel == 0) ? 0.125f : 1.0f;
    mma_gemm_body<1>(g_xhi, g_xlo, Bhi, Blo, bias, C, m0, n0, scale);
}

__global__ __launch_bounds__(256, 2) void out_mma(
    const float* __restrict__ bo, float* __restrict__ out)
{
    mma_gemm_body<0>(g_aohi, g_aolo, g_whi[3], g_wlo[3], bo, out,
                     blockIdx.y * BM, blockIdx.x * BN, 1.0f);
}

// =================================================================
// Flash attention (round-1 version, known-good: 560us)
// =================================================================
#define ABM 64
#define ABN 64
#define AST 68

__global__ __launch_bounds__(256) void attn_kernel(
    const float* __restrict__ Q, const float* __restrict__ K,
    const float* __restrict__ V, float* __restrict__ O)
{
    extern __shared__ float smem[];
    float (*Qt)[AST] = (float(*)[AST])(smem);
    float (*Kt)[AST] = (float(*)[AST])(smem + HD * AST);
    float (*Vs)[AST] = (float(*)[AST])(smem + 2 * HD * AST);
    float (*Ps)[AST] = (float(*)[AST])(smem + 3 * HD * AST);

    const int bh = blockIdx.y;
    const int qt = gridDim.x - 1 - (int)blockIdx.x;
    const int qbase = qt * ABM;

    const float* Qb = Q + (size_t)bh * SEQ * HD;
    const float* Kb = K + (size_t)bh * SEQ * HD;
    const float* Vb = V + (size_t)bh * SEQ * HD;

    const int tid = threadIdx.x;
    const int tr = tid >> 4, tc = tid & 15;
    const int r0 = tr * 4, c0 = tc * 4;

#pragma unroll
    for (int it = 0; it < 4; it++) {
        int e = it * 256 + tid;
        int d4 = (e >> 6) * 4;
        int n = e & 63;
        float4 v = *(const float4*)&Qb[(size_t)(qbase + n) * HD + d4];
        Qt[d4 + 0][n] = v.x; Qt[d4 + 1][n] = v.y;
        Qt[d4 + 2][n] = v.z; Qt[d4 + 3][n] = v.w;
    }

    float m_i[4], l_i[4], o[4][4];
#pragma unroll
    for (int i = 0; i < 4; i++) {
        m_i[i] = -1e30f;
        l_i[i] = 0.f;
#pragma unroll
        for (int j = 0; j < 4; j++) o[i][j] = 0.f;
    }

    for (int kt = 0; kt <= qt; kt++) {
        const int kbase = kt * ABN;
        __syncthreads();

#pragma unroll
        for (int it = 0; it < 4; it++) {
            int e = it * 256 + tid;
            int d4 = (e >> 6) * 4;
            int n = e & 63;
            float4 kv = *(const float4*)&Kb[(size_t)(kbase + n) * HD + d4];
            Kt[d4 + 0][n] = kv.x; Kt[d4 + 1][n] = kv.y;
            Kt[d4 + 2][n] = kv.z; Kt[d4 + 3][n] = kv.w;
            int n2 = e >> 4;
            int d42 = (e & 15) * 4;
            float4 vv = *(const float4*)&Vb[(size_t)(kbase + n2) * HD + d42];
            *(float4*)&Vs[n2][d42] = vv;
        }
        __syncthreads();

        float s[4][4];
#pragma unroll
        for (int i = 0; i < 4; i++)
#pragma unroll
            for (int j = 0; j < 4; j++) s[i][j] = 0.f;

#pragma unroll 8
        for (int d = 0; d < HD; d++) {
            float4 a = *(const float4*)&Qt[d][r0];
            float4 b = *(const float4*)&Kt[d][c0];
            float av[4] = {a.x, a.y, a.z, a.w};
            float bv[4] = {b.x, b.y, b.z, b.w};
#pragma unroll
            for (int i = 0; i < 4; i++)
#pragma unroll
                for (int j = 0; j < 4; j++)
                    s[i][j] = fmaf(av[i], bv[j], s[i][j]);
        }

        if (kt == qt) {
#pragma unroll
            for (int i = 0; i < 4; i++)
#pragma unroll
                for (int j = 0; j < 4; j++)
                    if (c0 + j > r0 + i) s[i][j] = -1e30f;
        }

#pragma unroll
        for (int i = 0; i < 4; i++) {
            float rm = fmaxf(fmaxf(s[i][0], s[i][1]), fmaxf(s[i][2], s[i][3]));
#pragma unroll
            for (int off = 1; off < 16; off <<= 1)
                rm = fmaxf(rm, __shfl_xor_sync(0xffffffffu, rm, off));
            float mn = fmaxf(m_i[i], rm);
            float corr = __expf(m_i[i] - mn);
            m_i[i] = mn;
            float rs = 0.f;
#pragma unroll
            for (int j = 0; j < 4; j++) {
                s[i][j] = __expf(s[i][j] - mn);
                rs += s[i][j];
            }
#pragma unroll
            for (int off = 1; off < 16; off <<= 1)
                rs += __shfl_xor_sync(0xffffffffu, rs, off);
            l_i[i] = l_i[i] * corr + rs;
#pragma unroll
            for (int j = 0; j < 4; j++) o[i][j] *= corr;
        }

#pragma unroll
        for (int i = 0; i < 4; i++)
            *(float4*)&Ps[r0 + i][c0] = make_float4(s[i][0], s[i][1], s[i][2], s[i][3]);
        __syncthreads();

#pragma unroll 4
        for (int cc = 0; cc < ABN; cc += 4) {
            float a[4][4];
#pragma unroll
            for (int i = 0; i < 4; i++)
                *(float4*)&a[i][0] = *(const float4*)&Ps[r0 + i][cc];
#pragma unroll
            for (int u = 0; u < 4; u++) {
                float4 bv = *(const float4*)&Vs[cc + u][c0];
                float bb[4] = {bv.x, bv.y, bv.z, bv.w};
#pragma unroll
                for (int i = 0; i < 4; i++)
#pragma unroll
                    for (int j = 0; j < 4; j++)
                        o[i][j] = fmaf(a[i][u], bb[j], o[i][j]);
            }
        }
    }

    const int b = bh / NH, h = bh % NH;
#pragma unroll
    for (int i = 0; i < 4; i++) {
        float inv = 1.f / l_i[i];
        int n = qbase + r0 + i;
        float* op = O + ((size_t)b * SEQ + n) * EMB + h * HD + c0;
        *(float4*)op = make_float4(o[i][0] * inv, o[i][1] * inv,
                                   o[i][2] * inv, o[i][3] * inv);
    }
}

// =================================================================
// launch
// =================================================================
extern "C" void kernel_launch(void* const* d_in, const int* in_sizes, int n_in,
                              void* d_out, int out_size)
{
    const float* x    = (const float*)d_in[0];
    const float* wq_w = (const float*)d_in[1];
    const float* wq_b = (const float*)d_in[2];
    const float* wk_w = (const float*)d_in[3];
    const float* wk_b = (const float*)d_in[4];
    const float* wv_w = (const float*)d_in[5];
    const float* wv_b = (const float*)d_in[6];
    const float* wo_w = (const float*)d_in[7];
    const float* wo_b = (const float*)d_in[8];
    float* out = (float*)d_out;

    float *q, *k, *v, *ao;
    bf16 *xhi, *xlo, *aohi, *aolo;
    cudaGetSymbolAddress((void**)&q, g_q);
    cudaGetSymbolAddress((void**)&k, g_k);
    cudaGetSymbolAddress((void**)&v, g_v);
    cudaGetSymbolAddress((void**)&ao, g_ao);
    cudaGetSymbolAddress((void**)&xhi, g_xhi);
    cudaGetSymbolAddress((void**)&xlo, g_xlo);
    cudaGetSymbolAddress((void**)&aohi, g_aohi);
    cudaGetSymbolAddress((void**)&aolo, g_aolo);

    const int attn_smem = 4 * HD * AST * (int)sizeof(float);
    cudaFuncSetAttribute(attn_kernel,
                         cudaFuncAttributeMaxDynamicSharedMemorySize, attn_smem);

    // conversions
    const int nx = MROWS * EMB;                    // 3,145,728
    split_kernel<<<(nx + 255) / 256, 256>>>(x, xhi, xlo, nx);
    dim3 gw((EMB * EMB + 255) / 256, 1, 4);        // 4 weights
    split_w_kernel<<<gw, 256>>>(wq_w, wk_w, wv_w, wo_w);

    // QKV projection (bf16-split MMA)
    dim3 gqkv(NQKV / BN, MROWS / BM);              // 18 x 32
    qkv_mma<<<gqkv, 256>>>(wq_b, wk_b, wv_b);

    // attention
    dim3 ga(SEQ / ABM, BATCH * NH);                // 32 x 24
    attn_kernel<<<ga, 256, attn_smem>>>(q, k, v, ao);

    // split attention output, then output projection
    split_kernel<<<(nx + 255) / 256, 256>>>(ao, aohi, aolo, nx);
    dim3 go(EMB / BN, MROWS / BM);                 // 6 x 32
    out_mma<<<go, 256>>>(wo_b, out);
}

// round 4
// speedup vs baseline: 3.8064x; 1.8710x over previous
#include <cuda_runtime.h>
#include <cuda_bf16.h>
#include <cstdint>

#define SEQ   2048
#define EMB   768
#define NH    12
#define HD    64
#define BATCH 2
#define MROWS (BATCH * SEQ)   // 4096
#define NQKV  (3 * EMB)       // 2304

typedef __nv_bfloat16 bf16;

// ---------------- scratch (static device arrays; no allocation) -------------
__device__ bf16 g_xhi[MROWS * EMB], g_xlo[MROWS * EMB];
__device__ bf16 g_whi[4][EMB * EMB], g_wlo[4][EMB * EMB];   // q,k,v,o
__device__ bf16 g_qhi[BATCH * NH * SEQ * HD], g_qlo[BATCH * NH * SEQ * HD];
__device__ bf16 g_khi[BATCH * NH * SEQ * HD], g_klo[BATCH * NH * SEQ * HD];
__device__ bf16 g_vhi[BATCH * NH * SEQ * HD], g_vlo[BATCH * NH * SEQ * HD];
__device__ bf16 g_aohi[MROWS * EMB], g_aolo[MROWS * EMB];

// ---------------- small helpers ----------------
__device__ __forceinline__ uint32_t cvt_bf2(float lo, float hi) {
    uint32_t r;
    asm("cvt.rn.bf16x2.f32 %0, %1, %2;" : "=r"(r) : "f"(hi), "f"(lo));
    return r;
}
__device__ __forceinline__ float bflo(uint32_t p) { return __uint_as_float(p << 16); }
__device__ __forceinline__ float bfhi(uint32_t p) { return __uint_as_float(p & 0xffff0000u); }
__device__ __forceinline__ float ex2f(float x) {
    float y;
    asm("ex2.approx.ftz.f32 %0, %1;" : "=f"(y) : "f"(x));
    return y;
}
__device__ __forceinline__ void ldsm4(uint32_t& r0, uint32_t& r1,
                                      uint32_t& r2, uint32_t& r3, uint32_t addr)
{
    asm volatile("ldmatrix.sync.aligned.m8n8.x4.shared.b16 {%0,%1,%2,%3}, [%4];"
                 : "=r"(r0), "=r"(r1), "=r"(r2), "=r"(r3) : "r"(addr));
}
__device__ __forceinline__ void ldsm4t(uint32_t& r0, uint32_t& r1,
                                       uint32_t& r2, uint32_t& r3, uint32_t addr)
{
    asm volatile("ldmatrix.sync.aligned.m8n8.x4.trans.shared.b16 {%0,%1,%2,%3}, [%4];"
                 : "=r"(r0), "=r"(r1), "=r"(r2), "=r"(r3) : "r"(addr));
}
__device__ __forceinline__ void mma16816(float c[4], const uint32_t a[4],
                                         uint32_t b0, uint32_t b1)
{
    asm volatile(
        "mma.sync.aligned.m16n8k16.row.col.f32.bf16.bf16.f32 "
        "{%0,%1,%2,%3}, {%4,%5,%6,%7}, {%8,%9}, {%0,%1,%2,%3};"
        : "+f"(c[0]), "+f"(c[1]), "+f"(c[2]), "+f"(c[3])
        : "r"(a[0]), "r"(a[1]), "r"(a[2]), "r"(a[3]), "r"(b0), "r"(b1));
}
__device__ __forceinline__ void cp16(uint32_t saddr, const void* gaddr)
{
    asm volatile("cp.async.cg.shared.global [%0], [%1], 16;"
                 :: "r"(saddr), "l"(gaddr));
}

// =================================================================
// fp32 -> bf16 hi/lo split conversions
// =================================================================
__global__ __launch_bounds__(256) void split_kernel(
    const float* __restrict__ src, bf16* __restrict__ hi,
    bf16* __restrict__ lo, int n)
{
    int i = blockIdx.x * 256 + threadIdx.x;
    if (i < n) {
        float v = src[i];
        bf16 h = __float2bfloat16(v);
        hi[i] = h;
        lo[i] = __float2bfloat16(v - __bfloat162float(h));
    }
}

__global__ __launch_bounds__(256) void split_w_kernel(
    const float* __restrict__ wq, const float* __restrict__ wk,
    const float* __restrict__ wv, const float* __restrict__ wo)
{
    int z = blockIdx.z;
    const float* src = (z == 0) ? wq : (z == 1) ? wk : (z == 2) ? wv : wo;
    bf16* hi = g_whi[z];
    bf16* lo = g_wlo[z];
    int i = blockIdx.x * 256 + threadIdx.x;
    if (i < EMB * EMB) {
        float v = src[i];
        bf16 h = __float2bfloat16(v);
        hi[i] = h;
        lo[i] = __float2bfloat16(v - __bfloat162float(h));
    }
}

// =================================================================
// bf16-split MMA GEMM (verified round 3). REMAP=1 -> write hi/lo bf16
// into head-major [bh][n][d]; REMAP=0 -> fp32 row-major out.
// =================================================================
#define BM 128
#define BN 128
#define BK 32
#define LDSK 40
#define NKB (EMB / BK)   // 24
#define NIT (3 * NKB)    // 72
#define BUF_ELEMS (BM * LDSK)

template<int REMAP>
__device__ __forceinline__ void mma_gemm_body(
    const bf16* __restrict__ Ahi, const bf16* __restrict__ Alo,
    const bf16* __restrict__ Bhi, const bf16* __restrict__ Blo,
    const float* __restrict__ bias, float* __restrict__ C,
    bf16* __restrict__ Chi, bf16* __restrict__ Clo,
    int m0, int n0, float scale)
{
    __shared__ bf16 As[2][BUF_ELEMS];
    __shared__ bf16 Bs[2][BUF_ELEMS];

    const int tid = threadIdx.x;
    const int lane = tid & 31;
    const int wid = tid >> 5;
    const int wm = wid >> 2;
    const int wn = wid & 3;

    float acc[4][4][4];
#pragma unroll
    for (int i = 0; i < 4; i++)
#pragma unroll
        for (int j = 0; j < 4; j++)
#pragma unroll
            for (int t = 0; t < 4; t++) acc[i][j][t] = 0.f;

    const int srow = tid >> 2;
    const int schk = (tid & 3) * 8;

    const uint32_t asb = (uint32_t)__cvta_generic_to_shared(&As[0][0]);
    const uint32_t bsb = (uint32_t)__cvta_generic_to_shared(&Bs[0][0]);

    const int laRow = wm * 64 + (lane & 15);
    const int laCol = (lane >> 4) * 8;
    const int lbRow = wn * 32 + ((lane >> 4) << 3) + (lane & 7);
    const int lbCol = ((lane >> 3) & 1) * 8;

#define ISSUE(IT, BUF)                                                        \
    do {                                                                      \
        int s_ = (IT) / NKB;                                                  \
        int k0_ = ((IT) - s_ * NKB) * BK;                                     \
        const bf16* Ap_ = (s_ == 2) ? Alo : Ahi;                              \
        const bf16* Bp_ = (s_ == 1) ? Blo : Bhi;                              \
        uint32_t sa_ = asb + (uint32_t)(BUF) * (BUF_ELEMS * 2);               \
        uint32_t sb_ = bsb + (uint32_t)(BUF) * (BUF_ELEMS * 2);               \
        cp16(sa_ + (srow * LDSK + schk) * 2,                                  \
             Ap_ + (size_t)(m0 + srow) * EMB + k0_ + schk);                   \
        cp16(sa_ + ((srow + 64) * LDSK + schk) * 2,                           \
             Ap_ + (size_t)(m0 + srow + 64) * EMB + k0_ + schk);              \
        cp16(sb_ + (srow * LDSK + schk) * 2,                                  \
             Bp_ + (size_t)(n0 + srow) * EMB + k0_ + schk);                   \
        cp16(sb_ + ((srow + 64) * LDSK + schk) * 2,                           \
             Bp_ + (size_t)(n0 + srow + 64) * EMB + k0_ + schk);              \
        asm volatile("cp.async.commit_group;");                               \
    } while (0)

    ISSUE(0, 0);

    for (int it = 0; it < NIT; it++) {
        const int buf = it & 1;
        if (it + 1 < NIT) {
            ISSUE(it + 1, buf ^ 1);
            asm volatile("cp.async.wait_group 1;");
        } else {
            asm volatile("cp.async.wait_group 0;");
        }
        __syncthreads();

        const uint32_t sa = asb + (uint32_t)buf * (BUF_ELEMS * 2);
        const uint32_t sb = bsb + (uint32_t)buf * (BUF_ELEMS * 2);

#pragma unroll
        for (int ks = 0; ks < 2; ks++) {
            uint32_t a[4][4];
#pragma unroll
            for (int mt = 0; mt < 4; mt++)
                ldsm4(a[mt][0], a[mt][1], a[mt][2], a[mt][3],
                      sa + (uint32_t)(((laRow + mt * 16) * LDSK) + ks * 16 + laCol) * 2);
            uint32_t b[2][4];
#pragma unroll
            for (int p = 0; p < 2; p++)
                ldsm4(b[p][0], b[p][1], b[p][2], b[p][3],
                      sb + (uint32_t)(((lbRow + p * 16) * LDSK) + ks * 16 + lbCol) * 2);
#pragma unroll
            for (int mt = 0; mt < 4; mt++)
#pragma unroll
                for (int nt = 0; nt < 4; nt++)
                    mma16816(acc[mt][nt], a[mt],
                             b[nt >> 1][(nt & 1) * 2], b[nt >> 1][(nt & 1) * 2 + 1]);
        }
        __syncthreads();
    }
#undef ISSUE

    const int er = lane >> 2;
    const int ec = (lane & 3) * 2;
#pragma unroll
    for (int mt = 0; mt < 4; mt++) {
        int m = m0 + wm * 64 + mt * 16 + er;
#pragma unroll
        for (int nt = 0; nt < 4; nt++) {
            int n = n0 + wn * 32 + nt * 8 + ec;
            float b0 = bias[n], b1 = bias[n + 1];
            float v00 = (acc[mt][nt][0] + b0) * scale;
            float v01 = (acc[mt][nt][1] + b1) * scale;
            float v10 = (acc[mt][nt][2] + b0) * scale;
            float v11 = (acc[mt][nt][3] + b1) * scale;
            if (REMAP) {
                int h = n >> 6, d = n & 63;
                int bb0 = m >> 11, s0 = m & 2047;
                int bb1 = (m + 8) >> 11, s1 = (m + 8) & 2047;
                size_t p0 = (((size_t)(bb0 * NH + h)) * SEQ + s0) * HD + d;
                size_t p1 = (((size_t)(bb1 * NH + h)) * SEQ + s1) * HD + d;
                uint32_t hp = cvt_bf2(v00, v01);
                uint32_t lp = cvt_bf2(v00 - bflo(hp), v01 - bfhi(hp));
                *(uint32_t*)&Chi[p0] = hp;
                *(uint32_t*)&Clo[p0] = lp;
                hp = cvt_bf2(v10, v11);
                lp = cvt_bf2(v10 - bflo(hp), v11 - bfhi(hp));
                *(uint32_t*)&Chi[p1] = hp;
                *(uint32_t*)&Clo[p1] = lp;
            } else {
                *(float2*)&C[(size_t)m * EMB + n] = make_float2(v00, v01);
                *(float2*)&C[(size_t)(m + 8) * EMB + n] = make_float2(v10, v11);
            }
        }
    }
}

__global__ __launch_bounds__(256, 2) void qkv_mma(
    const float* __restrict__ bq, const float* __restrict__ bk,
    const float* __restrict__ bv)
{
    int m0 = blockIdx.y * BM;
    int ng = blockIdx.x * BN;
    int sel = ng / EMB;
    int n0 = ng - sel * EMB;
    const bf16* Bhi = g_whi[sel];
    const bf16* Blo = g_wlo[sel];
    const float* bias = (sel == 0) ? bq : (sel == 1) ? bk : bv;
    bf16* Chi = (sel == 0) ? g_qhi : (sel == 1) ? g_khi : g_vhi;
    bf16* Clo = (sel == 0) ? g_qlo : (sel == 1) ? g_klo : g_vlo;
    // fold 1/sqrt(d) and log2(e) into q -> softmax uses raw ex2
    float scale = (sel == 0) ? 0.125f * 1.4426950408889634f : 1.0f;
    mma_gemm_body<1>(g_xhi, g_xlo, Bhi, Blo, bias, nullptr, Chi, Clo,
                     m0, n0, scale);
}

__global__ __launch_bounds__(256, 2) void out_mma(
    const float* __restrict__ bo, float* __restrict__ out)
{
    mma_gemm_body<0>(g_aohi, g_aolo, g_whi[3], g_wlo[3], bo, out,
                     nullptr, nullptr, blockIdx.y * BM, blockIdx.x * BN, 1.0f);
}

// =================================================================
// Tensor-core flash attention (causal, online softmax, log2 domain).
// 128-row q-tiles, 64-key tiles, 8 warps x 16-row strips.
// S: Qhi*Khi + Qhi*Klo + Qlo*Khi (Q frags register-resident).
// PV: Phi*Vhi + Phi*Vlo + Plo*Vhi (P split in registers, V via ldsm.trans).
// Q smem region reused as the K/V double buffer.
// =================================================================
#define STR 72   // smem row stride in bf16 elems (144B: conflict-free ldmatrix)
#define ATT_SMEM (512 * STR * 2)   // 73728 B

__device__ __forceinline__ void kv_issue(uint32_t sb, int buf, int kbase,
                                         const bf16* const kvsrc[4], int tid)
{
    uint32_t base = sb + (uint32_t)buf * (256 * STR * 2);
#pragma unroll
    for (int i = 0; i < 8; i++) {
        int c = i * 256 + tid;
        int row = (c >> 3) & 63;
        int ch = (c & 7) * 8;
        cp16(base + (uint32_t)(((i >> 1) * 64 + row) * STR + ch) * 2,
             kvsrc[i >> 1] + (size_t)(kbase + row) * HD + ch);
    }
    asm volatile("cp.async.commit_group;");
}

__global__ __launch_bounds__(256, 2) void attn_mma(
    const bf16* __restrict__ Qhi_g, const bf16* __restrict__ Qlo_g,
    const bf16* __restrict__ Khi_g, const bf16* __restrict__ Klo_g,
    const bf16* __restrict__ Vhi_g, const bf16* __restrict__ Vlo_g,
    bf16* __restrict__ AOhi, bf16* __restrict__ AOlo)
{
    extern __shared__ bf16 sm[];
    const uint32_t sb = (uint32_t)__cvta_generic_to_shared(sm);

    const int bh = blockIdx.y;
    const int qt = (int)gridDim.x - 1 - (int)blockIdx.x;   // heavy tiles first
    const int qbase = qt * 128;
    const int nkt = 2 * qt + 2;

    const int tid = threadIdx.x;
    const int lane = tid & 31;
    const int wid = tid >> 5;
    const int wr = wid * 16;

    const size_t hoff = (size_t)bh * SEQ * HD;
    const bf16* qsrc[2] = {Qhi_g + hoff, Qlo_g + hoff};
    const bf16* kvsrc[4] = {Khi_g + hoff, Klo_g + hoff, Vhi_g + hoff, Vlo_g + hoff};

    // ---- stage Q (hi rows 0..127, lo rows 128..255) ----
#pragma unroll
    for (int i = 0; i < 8; i++) {
        int c = i * 256 + tid;
        int row = (c >> 3) & 127;
        int ch = (c & 7) * 8;
        cp16(sb + (uint32_t)(((i >> 2) * 128 + row) * STR + ch) * 2,
             qsrc[i >> 2] + (size_t)(qbase + row) * HD + ch);
    }
    asm volatile("cp.async.commit_group;");
    asm volatile("cp.async.wait_group 0;");
    __syncthreads();

    // ---- Q fragments (held in registers for the whole kernel) ----
    uint32_t qh[4][4], ql[4][4];
    {
        int arow = wr + (lane & 15);
        int acol = (lane >> 4) * 8;
#pragma unroll
        for (int ks = 0; ks < 4; ks++) {
            ldsm4(qh[ks][0], qh[ks][1], qh[ks][2], qh[ks][3],
                  sb + (uint32_t)(arow * STR + ks * 16 + acol) * 2);
            ldsm4(ql[ks][0], ql[ks][1], ql[ks][2], ql[ks][3],
                  sb + (uint32_t)((128 + arow) * STR + ks * 16 + acol) * 2);
        }
    }
    __syncthreads();   // Q reads done; region becomes KV buffer 0

    float o[8][4];
#pragma unroll
    for (int i = 0; i < 8; i++)
#pragma unroll
        for (int j = 0; j < 4; j++) o[i][j] = 0.f;
    float m0 = -1e30f, m1 = -1e30f, l0 = 0.f, l1 = 0.f;

    kv_issue(sb, 0, 0, kvsrc, tid);

    const int brow = (lane & 7) + ((lane >> 4) << 3);       // K ldsm row
    const int bcol = ((lane >> 3) & 1) * 8;                 // K ldsm col
    const int vrow = (lane & 7) + (((lane >> 3) & 1) << 3); // V trans row
    const int vcol = (lane >> 4) * 8;                       // V trans col

    for (int kt = 0; kt < nkt; kt++) {
        if (kt + 1 < nkt) {
            kv_issue(sb, (kt + 1) & 1, (kt + 1) * 64, kvsrc, tid);
            asm volatile("cp.async.wait_group 1;");
        } else {
            asm volatile("cp.async.wait_group 0;");
        }
        __syncthreads();

        const uint32_t kvb = sb + (uint32_t)(kt & 1) * (256 * STR * 2);
        const uint32_t Khi_s = kvb;
        const uint32_t Klo_s = kvb + 64 * STR * 2;
        const uint32_t Vhi_s = kvb + 128 * STR * 2;
        const uint32_t Vlo_s = kvb + 192 * STR * 2;
        const int kbase = kt * 64;

        // ---- S = Q K^T (3-pass split) ----
        float s[8][4];
#pragma unroll
        for (int i = 0; i < 8; i++)
#pragma unroll
            for (int j = 0; j < 4; j++) s[i][j] = 0.f;

#pragma unroll
        for (int ks = 0; ks < 4; ks++) {
            uint32_t bb[4][4];
#pragma unroll
            for (int ng = 0; ng < 4; ng++)
                ldsm4(bb[ng][0], bb[ng][1], bb[ng][2], bb[ng][3],
                      Khi_s + (uint32_t)((16 * ng + brow) * STR + 16 * ks + bcol) * 2);
#pragma unroll
            for (int ng = 0; ng < 4; ng++) {
                mma16816(s[2 * ng], qh[ks], bb[ng][0], bb[ng][1]);
                mma16816(s[2 * ng + 1], qh[ks], bb[ng][2], bb[ng][3]);
                mma16816(s[2 * ng], ql[ks], bb[ng][0], bb[ng][1]);
                mma16816(s[2 * ng + 1], ql[ks], bb[ng][2], bb[ng][3]);
            }
#pragma unroll
            for (int ng = 0; ng < 4; ng++)
                ldsm4(bb[ng][0], bb[ng][1], bb[ng][2], bb[ng][3],
                      Klo_s + (uint32_t)((16 * ng + brow) * STR + 16 * ks + bcol) * 2);
#pragma unroll
            for (int ng = 0; ng < 4; ng++) {
                mma16816(s[2 * ng], qh[ks], bb[ng][0], bb[ng][1]);
                mma16816(s[2 * ng + 1], qh[ks], bb[ng][2], bb[ng][3]);
            }
        }

        // ---- causal mask (only tiles overlapping the diagonal) ----
        if (kbase + 63 > qbase + wr) {
            int row0 = qbase + wr + (lane >> 2);
            int colb = kbase + 2 * (lane & 3);
#pragma unroll
            for (int nt = 0; nt < 8; nt++) {
                int c0 = colb + nt * 8;
                if (c0 > row0) s[nt][0] = -1e30f;
                if (c0 + 1 > row0) s[nt][1] = -1e30f;
                if (c0 > row0 + 8) s[nt][2] = -1e30f;
                if (c0 + 1 > row0 + 8) s[nt][3] = -1e30f;
            }
        }

        // ---- online softmax (log2 domain) ----
        float mx0 = s[0][0], mx1 = s[0][2];
#pragma unroll
        for (int nt = 0; nt < 8; nt++) {
            mx0 = fmaxf(mx0, fmaxf(s[nt][0], s[nt][1]));
            mx1 = fmaxf(mx1, fmaxf(s[nt][2], s[nt][3]));
        }
        mx0 = fmaxf(mx0, __shfl_xor_sync(0xffffffffu, mx0, 1));
        mx0 = fmaxf(mx0, __shfl_xor_sync(0xffffffffu, mx0, 2));
        mx1 = fmaxf(mx1, __shfl_xor_sync(0xffffffffu, mx1, 1));
        mx1 = fmaxf(mx1, __shfl_xor_sync(0xffffffffu, mx1, 2));
        float mn0 = fmaxf(m0, mx0), mn1 = fmaxf(m1, mx1);
        float corr0 = ex2f(m0 - mn0), corr1 = ex2f(m1 - mn1);
        m0 = mn0; m1 = mn1;
        float rs0 = 0.f, rs1 = 0.f;
#pragma unroll
        for (int nt = 0; nt < 8; nt++) {
            s[nt][0] = ex2f(s[nt][0] - mn0); rs0 += s[nt][0];
            s[nt][1] = ex2f(s[nt][1] - mn0); rs0 += s[nt][1];
            s[nt][2] = ex2f(s[nt][2] - mn1); rs1 += s[nt][2];
            s[nt][3] = ex2f(s[nt][3] - mn1); rs1 += s[nt][3];
        }
        rs0 += __shfl_xor_sync(0xffffffffu, rs0, 1);
        rs0 += __shfl_xor_sync(0xffffffffu, rs0, 2);
        rs1 += __shfl_xor_sync(0xffffffffu, rs1, 1);
        rs1 += __shfl_xor_sync(0xffffffffu, rs1, 2);
        l0 = l0 * corr0 + rs0;
        l1 = l1 * corr1 + rs1;
#pragma unroll
        for (int nd = 0; nd < 8; nd++) {
            o[nd][0] *= corr0; o[nd][1] *= corr0;
            o[nd][2] *= corr1; o[nd][3] *= corr1;
        }

        // ---- P -> bf16 hi/lo A-fragments (pure register work) ----
        uint32_t phi[4][4], plo[4][4];
#pragma unroll
        for (int t = 0; t < 4; t++) {
#pragma unroll
            for (int half = 0; half < 2; half++) {
                const float* sp = s[2 * t + half];
                // a-regs: [0]=(r,c) [1]=(r+8,c) from ntile 2t; [2],[3] from 2t+1
                int i0 = half * 2, i1 = half * 2 + 1;
                uint32_t h0 = cvt_bf2(sp[0], sp[1]);
                phi[t][i0] = h0;
                plo[t][i0] = cvt_bf2(sp[0] - bflo(h0), sp[1] - bfhi(h0));
                uint32_t h1 = cvt_bf2(sp[2], sp[3]);
                phi[t][i1] = h1;
                plo[t][i1] = cvt_bf2(sp[2] - bflo(h1), sp[3] - bfhi(h1));
            }
        }

        // ---- O += P V (3-pass split, V via ldmatrix.trans) ----
#pragma unroll
        for (int t = 0; t < 4; t++) {
            uint32_t vb[4][4];
#pragma unroll
            for (int g = 0; g < 4; g++)
                ldsm4t(vb[g][0], vb[g][1], vb[g][2], vb[g][3],
                       Vhi_s + (uint32_t)((16 * t + vrow) * STR + 16 * g + vcol) * 2);
#pragma unroll
            for (int g = 0; g < 4; g++) {
                mma16816(o[2 * g], phi[t], vb[g][0], vb[g][1]);
                mma16816(o[2 * g + 1], phi[t], vb[g][2], vb[g][3]);
                mma16816(o[2 * g], plo[t], vb[g][0], vb[g][1]);
                mma16816(o[2 * g + 1], plo[t], vb[g][2], vb[g][3]);
            }
#pragma unroll
            for (int g = 0; g < 4; g++)
                ldsm4t(vb[g][0], vb[g][1], vb[g][2], vb[g][3],
                       Vlo_s + (uint32_t)((16 * t + vrow) * STR + 16 * g + vcol) * 2);
#pragma unroll
            for (int g = 0; g < 4; g++) {
                mma16816(o[2 * g], phi[t], vb[g][0], vb[g][1]);
                mma16816(o[2 * g + 1], phi[t], vb[g][2], vb[g][3]);
            }
        }

        __syncthreads();   // all reads of this buffer done before re-fill
    }

    // ---- epilogue: write ao pre-split hi/lo, [b][n][emb] ----
    float inv0 = 1.f / l0, inv1 = 1.f / l1;
    int b = bh / NH, h = bh % NH;
    int row0 = qbase + wr + (lane >> 2);
    size_t off0 = ((size_t)b * SEQ + row0) * EMB + h * HD + 2 * (lane & 3);
    size_t off1 = off0 + 8 * (size_t)EMB;
#pragma unroll
    for (int nd = 0; nd < 8; nd++) {
        float f0 = o[nd][0] * inv0, f1 = o[nd][1] * inv0;
        uint32_t hp = cvt_bf2(f0, f1);
        uint32_t lp = cvt_bf2(f0 - bflo(hp), f1 - bfhi(hp));
        *(uint32_t*)&AOhi[off0 + nd * 8] = hp;
        *(uint32_t*)&AOlo[off0 + nd * 8] = lp;
        float g0 = o[nd][2] * inv1, g1 = o[nd][3] * inv1;
        uint32_t hq = cvt_bf2(g0, g1);
        uint32_t lq = cvt_bf2(g0 - bflo(hq), g1 - bfhi(hq));
        *(uint32_t*)&AOhi[off1 + nd * 8] = hq;
        *(uint32_t*)&AOlo[off1 + nd * 8] = lq;
    }
}

// =================================================================
// launch
// =================================================================
extern "C" void kernel_launch(void* const* d_in, const int* in_sizes, int n_in,
                              void* d_out, int out_size)
{
    const float* x    = (const float*)d_in[0];
    const float* wq_b = (const float*)d_in[2];
    const float* wk_b = (const float*)d_in[4];
    const float* wv_b = (const float*)d_in[6];
    const float* wo_b = (const float*)d_in[8];
    float* out = (float*)d_out;

    bf16 *xhi, *xlo;
    bf16 *qhi, *qlo, *khi, *klo, *vhi, *vlo, *aohi, *aolo;
    cudaGetSymbolAddress((void**)&xhi, g_xhi);
    cudaGetSymbolAddress((void**)&xlo, g_xlo);
    cudaGetSymbolAddress((void**)&qhi, g_qhi);
    cudaGetSymbolAddress((void**)&qlo, g_qlo);
    cudaGetSymbolAddress((void**)&khi, g_khi);
    cudaGetSymbolAddress((void**)&klo, g_klo);
    cudaGetSymbolAddress((void**)&vhi, g_vhi);
    cudaGetSymbolAddress((void**)&vlo, g_vlo);
    cudaGetSymbolAddress((void**)&aohi, g_aohi);
    cudaGetSymbolAddress((void**)&aolo, g_aolo);

    cudaFuncSetAttribute(attn_mma,
                         cudaFuncAttributeMaxDynamicSharedMemorySize, ATT_SMEM);

    // conversions
    const int nx = MROWS * EMB;
    split_kernel<<<(nx + 255) / 256, 256>>>(x, xhi, xlo, nx);
    dim3 gw((EMB * EMB + 255) / 256, 1, 4);
    split_w_kernel<<<gw, 256>>>((const float*)d_in[1], (const float*)d_in[3],
                                (const float*)d_in[5], (const float*)d_in[7]);

    // QKV projection (writes pre-split q/k/v hi+lo)
    dim3 gqkv(NQKV / BN, MROWS / BM);              // 18 x 32
    qkv_mma<<<gqkv, 256>>>(wq_b, wk_b, wv_b);

    // attention (tensor cores)
    dim3 ga(SEQ / 128, BATCH * NH);                // 16 x 24
    attn_mma<<<ga, 256, ATT_SMEM>>>(qhi, qlo, khi, klo, vhi, vlo, aohi, aolo);

    // output projection
    dim3 go(EMB / BN, MROWS / BM);                 // 6 x 32
    out_mma<<<go, 256>>>(wo_b, out);
}

// round 6
// speedup vs baseline: 4.1507x; 1.0905x over previous
#include <cuda_runtime.h>
#include <cuda_bf16.h>
#include <cstdint>

#define SEQ   2048
#define EMB   768
#define NH    12
#define HD    64
#define BATCH 2
#define MROWS (BATCH * SEQ)   // 4096
#define NQKV  (3 * EMB)       // 2304

typedef __nv_bfloat16 bf16;

// ---------------- scratch (static device arrays; no allocation) -------------
__device__ bf16 g_xhi[MROWS * EMB], g_xlo[MROWS * EMB];
__device__ bf16 g_whi[4][EMB * EMB], g_wlo[4][EMB * EMB];   // q,k,v,o
__device__ bf16 g_qhi[BATCH * NH * SEQ * HD], g_qlo[BATCH * NH * SEQ * HD];
__device__ bf16 g_khi[BATCH * NH * SEQ * HD], g_klo[BATCH * NH * SEQ * HD];
__device__ bf16 g_vhi[BATCH * NH * SEQ * HD], g_vlo[BATCH * NH * SEQ * HD];
__device__ bf16 g_aohi[MROWS * EMB], g_aolo[MROWS * EMB];

// ---------------- small helpers ----------------
__device__ __forceinline__ uint32_t cvt_bf2(float lo, float hi) {
    uint32_t r;
    asm("cvt.rn.bf16x2.f32 %0, %1, %2;" : "=r"(r) : "f"(hi), "f"(lo));
    return r;
}
__device__ __forceinline__ float bflo(uint32_t p) { return __uint_as_float(p << 16); }
__device__ __forceinline__ float bfhi(uint32_t p) { return __uint_as_float(p & 0xffff0000u); }
__device__ __forceinline__ float ex2f(float x) {
    float y;
    asm("ex2.approx.ftz.f32 %0, %1;" : "=f"(y) : "f"(x));
    return y;
}
__device__ __forceinline__ void ldsm4(uint32_t& r0, uint32_t& r1,
                                      uint32_t& r2, uint32_t& r3, uint32_t addr)
{
    asm volatile("ldmatrix.sync.aligned.m8n8.x4.shared.b16 {%0,%1,%2,%3}, [%4];"
                 : "=r"(r0), "=r"(r1), "=r"(r2), "=r"(r3) : "r"(addr));
}
__device__ __forceinline__ void ldsm4t(uint32_t& r0, uint32_t& r1,
                                       uint32_t& r2, uint32_t& r3, uint32_t addr)
{
    asm volatile("ldmatrix.sync.aligned.m8n8.x4.trans.shared.b16 {%0,%1,%2,%3}, [%4];"
                 : "=r"(r0), "=r"(r1), "=r"(r2), "=r"(r3) : "r"(addr));
}
__device__ __forceinline__ void mma16816(float c[4], const uint32_t a[4],
                                         uint32_t b0, uint32_t b1)
{
    asm volatile(
        "mma.sync.aligned.m16n8k16.row.col.f32.bf16.bf16.f32 "
        "{%0,%1,%2,%3}, {%4,%5,%6,%7}, {%8,%9}, {%0,%1,%2,%3};"
        : "+f"(c[0]), "+f"(c[1]), "+f"(c[2]), "+f"(c[3])
        : "r"(a[0]), "r"(a[1]), "r"(a[2]), "r"(a[3]), "r"(b0), "r"(b1));
}
__device__ __forceinline__ void cp16(uint32_t saddr, const void* gaddr)
{
    asm volatile("cp.async.cg.shared.global [%0], [%1], 16;"
                 :: "r"(saddr), "l"(gaddr));
}
template<int N>
__device__ __forceinline__ void cp_wait()
{
    asm volatile("cp.async.wait_group %0;" :: "n"(N));
}

// =================================================================
// fp32 -> bf16 hi/lo split conversions (float4 vectorized)
// =================================================================
__global__ __launch_bounds__(256) void split4_kernel(
    const float4* __restrict__ src, uint2* __restrict__ hi,
    uint2* __restrict__ lo, int n4)
{
    int i = blockIdx.x * 256 + threadIdx.x;
    if (i < n4) {
        float4 v = src[i];
        uint32_t h0 = cvt_bf2(v.x, v.y);
        uint32_t h1 = cvt_bf2(v.z, v.w);
        uint32_t l0 = cvt_bf2(v.x - bflo(h0), v.y - bfhi(h0));
        uint32_t l1 = cvt_bf2(v.z - bflo(h1), v.w - bfhi(h1));
        hi[i] = make_uint2(h0, h1);
        lo[i] = make_uint2(l0, l1);
    }
}

__global__ __launch_bounds__(256) void split_w4_kernel(
    const float* __restrict__ wq, const float* __restrict__ wk,
    const float* __restrict__ wv, const float* __restrict__ wo)
{
    int z = blockIdx.z;
    const float4* src = (const float4*)((z == 0) ? wq : (z == 1) ? wk :
                                        (z == 2) ? wv : wo);
    uint2* hi = (uint2*)g_whi[z];
    uint2* lo = (uint2*)g_wlo[z];
    int i = blockIdx.x * 256 + threadIdx.x;
    if (i < EMB * EMB / 4) {
        float4 v = src[i];
        uint32_t h0 = cvt_bf2(v.x, v.y);
        uint32_t h1 = cvt_bf2(v.z, v.w);
        uint32_t l0 = cvt_bf2(v.x - bflo(h0), v.y - bfhi(h0));
        uint32_t l1 = cvt_bf2(v.z - bflo(h1), v.w - bfhi(h1));
        hi[i] = make_uint2(h0, h1);
        lo[i] = make_uint2(l0, l1);
    }
}

// =================================================================
// bf16-split MMA GEMM (3-stage cp.async ring, one sync/iter)
// Tiles: BM=128, BN=128, BK=32. 8 warps (2m x 4n), warp tile 64x32.
// =================================================================
#define BM 128
#define BN 128
#define BK 32
#define LDSK 40
#define NKB (EMB / BK)   // 24
#define NIT (3 * NKB)    // 72
#define BUF_ELEMS (BM * LDSK)        // 5120 bf16
#define GSTAGE_B (BUF_ELEMS * 2)     // 10240 bytes per matrix per stage
#define GEMM_SMEM (6 * GSTAGE_B)     // 61440

__device__ __forceinline__ void gemm_issue(
    int it, int buf,
    const bf16* __restrict__ Ahi, const bf16* __restrict__ Alo,
    const bf16* __restrict__ Bhi, const bf16* __restrict__ Blo,
    uint32_t asb, uint32_t bsb, int m0, int n0, int srow, int schk)
{
    int s_ = it / NKB;
    int k0_ = (it - s_ * NKB) * BK;
    const bf16* Ap = (s_ == 2) ? Alo : Ahi;
    const bf16* Bp = (s_ == 1) ? Blo : Bhi;
    uint32_t sa = asb + (uint32_t)buf * GSTAGE_B;
    uint32_t sb = bsb + (uint32_t)buf * GSTAGE_B;
    cp16(sa + (srow * LDSK + schk) * 2,
         Ap + (size_t)(m0 + srow) * EMB + k0_ + schk);
    cp16(sa + ((srow + 64) * LDSK + schk) * 2,
         Ap + (size_t)(m0 + srow + 64) * EMB + k0_ + schk);
    cp16(sb + (srow * LDSK + schk) * 2,
         Bp + (size_t)(n0 + srow) * EMB + k0_ + schk);
    cp16(sb + ((srow + 64) * LDSK + schk) * 2,
         Bp + (size_t)(n0 + srow + 64) * EMB + k0_ + schk);
    asm volatile("cp.async.commit_group;");
}

template<int REMAP>
__device__ __forceinline__ void mma_gemm_body(
    const bf16* __restrict__ Ahi, const bf16* __restrict__ Alo,
    const bf16* __restrict__ Bhi, const bf16* __restrict__ Blo,
    const float* __restrict__ bias, float* __restrict__ C,
    bf16* __restrict__ Chi, bf16* __restrict__ Clo,
    int m0, int n0, float scale)
{
    extern __shared__ char dsm[];
    const uint32_t asb = (uint32_t)__cvta_generic_to_shared(dsm);
    const uint32_t bsb = asb + 3 * GSTAGE_B;

    const int tid = threadIdx.x;
    const int lane = tid & 31;
    const int wid = tid >> 5;
    const int wm = wid >> 2;
    const int wn = wid & 3;

    float acc[4][4][4];
#pragma unroll
    for (int i = 0; i < 4; i++)
#pragma unroll
        for (int j = 0; j < 4; j++)
#pragma unroll
            for (int t = 0; t < 4; t++) acc[i][j][t] = 0.f;

    const int srow = tid >> 2;
    const int schk = (tid & 3) * 8;

    const int laRow = wm * 64 + (lane & 15);
    const int laCol = (lane >> 4) * 8;
    const int lbRow = wn * 32 + ((lane >> 4) << 3) + (lane & 7);
    const int lbCol = ((lane >> 3) & 1) * 8;

    gemm_issue(0, 0, Ahi, Alo, Bhi, Blo, asb, bsb, m0, n0, srow, schk);
    gemm_issue(1, 1, Ahi, Alo, Bhi, Blo, asb, bsb, m0, n0, srow, schk);

    int st = 0;
    for (int it = 0; it < NIT; it++) {
        if (it + 1 < NIT) cp_wait<1>(); else cp_wait<0>();
        __syncthreads();
        if (it + 2 < NIT) {
            int b2 = st + 2; if (b2 >= 3) b2 -= 3;
            gemm_issue(it + 2, b2, Ahi, Alo, Bhi, Blo, asb, bsb,
                       m0, n0, srow, schk);
        }

        const uint32_t sa = asb + (uint32_t)st * GSTAGE_B;
        const uint32_t sb = bsb + (uint32_t)st * GSTAGE_B;

#pragma unroll
        for (int ks = 0; ks < 2; ks++) {
            uint32_t a[4][4];
#pragma unroll
            for (int mt = 0; mt < 4; mt++)
                ldsm4(a[mt][0], a[mt][1], a[mt][2], a[mt][3],
                      sa + (uint32_t)(((laRow + mt * 16) * LDSK) + ks * 16 + laCol) * 2);
            uint32_t b[2][4];
#pragma unroll
            for (int p = 0; p < 2; p++)
                ldsm4(b[p][0], b[p][1], b[p][2], b[p][3],
                      sb + (uint32_t)(((lbRow + p * 16) * LDSK) + ks * 16 + lbCol) * 2);
#pragma unroll
            for (int mt = 0; mt < 4; mt++)
#pragma unroll
                for (int nt = 0; nt < 4; nt++)
                    mma16816(acc[mt][nt], a[mt],
                             b[nt >> 1][(nt & 1) * 2], b[nt >> 1][(nt & 1) * 2 + 1]);
        }
        st = (st + 1 == 3) ? 0 : st + 1;
    }

    const int er = lane >> 2;
    const int ec = (lane & 3) * 2;
#pragma unroll
    for (int mt = 0; mt < 4; mt++) {
        int m = m0 + wm * 64 + mt * 16 + er;
#pragma unroll
        for (int nt = 0; nt < 4; nt++) {
            int n = n0 + wn * 32 + nt * 8 + ec;
            float b0 = bias[n], b1 = bias[n + 1];
            float v00 = (acc[mt][nt][0] + b0) * scale;
            float v01 = (acc[mt][nt][1] + b1) * scale;
            float v10 = (acc[mt][nt][2] + b0) * scale;
            float v11 = (acc[mt][nt][3] + b1) * scale;
            if (REMAP) {
                int h = n >> 6, d = n & 63;
                int bb0 = m >> 11, s0 = m & 2047;
                int bb1 = (m + 8) >> 11, s1 = (m + 8) & 2047;
                size_t p0 = (((size_t)(bb0 * NH + h)) * SEQ + s0) * HD + d;
                size_t p1 = (((size_t)(bb1 * NH + h)) * SEQ + s1) * HD + d;
                uint32_t hp = cvt_bf2(v00, v01);
                uint32_t lp = cvt_bf2(v00 - bflo(hp), v01 - bfhi(hp));
                *(uint32_t*)&Chi[p0] = hp;
                *(uint32_t*)&Clo[p0] = lp;
                hp = cvt_bf2(v10, v11);
                lp = cvt_bf2(v10 - bflo(hp), v11 - bfhi(hp));
                *(uint32_t*)&Chi[p1] = hp;
                *(uint32_t*)&Clo[p1] = lp;
            } else {
                *(float2*)&C[(size_t)m * EMB + n] = make_float2(v00, v01);
                *(float2*)&C[(size_t)(m + 8) * EMB + n] = make_float2(v10, v11);
            }
        }
    }
}

__global__ __launch_bounds__(256, 2) void qkv_mma(
    const float* __restrict__ bq, const float* __restrict__ bk,
    const float* __restrict__ bv)
{
    int m0 = blockIdx.y * BM;
    int ng = blockIdx.x * BN;
    int sel = ng / EMB;
    int n0 = ng - sel * EMB;
    const bf16* Bhi = g_whi[sel];
    const bf16* Blo = g_wlo[sel];
    const float* bias = (sel == 0) ? bq : (sel == 1) ? bk : bv;
    bf16* Chi = (sel == 0) ? g_qhi : (sel == 1) ? g_khi : g_vhi;
    bf16* Clo = (sel == 0) ? g_qlo : (sel == 1) ? g_klo : g_vlo;
    float scale = (sel == 0) ? 0.125f * 1.4426950408889634f : 1.0f;
    mma_gemm_body<1>(g_xhi, g_xlo, Bhi, Blo, bias, nullptr, Chi, Clo,
                     m0, n0, scale);
}

__global__ __launch_bounds__(256, 2) void out_mma(
    const float* __restrict__ bo, float* __restrict__ out)
{
    mma_gemm_body<0>(g_aohi, g_aolo, g_whi[3], g_wlo[3], bo, out,
                     nullptr, nullptr, blockIdx.y * BM, blockIdx.x * BN, 1.0f);
}

// =================================================================
// Tensor-core flash attention (3-stage KV ring, one sync/iter)
// =================================================================
#define STR 72
#define KV_STAGE_B (256 * STR * 2)       // 36864
#define ATT_SMEM (3 * KV_STAGE_B)        // 110592

__device__ __forceinline__ void kv_issue(uint32_t sb, int buf, int kbase,
                                         const bf16* const kvsrc[4], int tid)
{
    uint32_t base = sb + (uint32_t)buf * KV_STAGE_B;
#pragma unroll
    for (int i = 0; i < 8; i++) {
        int c = i * 256 + tid;
        int row = (c >> 3) & 63;
        int ch = (c & 7) * 8;
        cp16(base + (uint32_t)(((i >> 1) * 64 + row) * STR + ch) * 2,
             kvsrc[i >> 1] + (size_t)(kbase + row) * HD + ch);
    }
    asm volatile("cp.async.commit_group;");
}

__global__ __launch_bounds__(256, 2) void attn_mma(
    const bf16* __restrict__ Qhi_g, const bf16* __restrict__ Qlo_g,
    const bf16* __restrict__ Khi_g, const bf16* __restrict__ Klo_g,
    const bf16* __restrict__ Vhi_g, const bf16* __restrict__ Vlo_g,
    bf16* __restrict__ AOhi, bf16* __restrict__ AOlo)
{
    extern __shared__ char dsm[];
    const uint32_t sb = (uint32_t)__cvta_generic_to_shared(dsm);

    const int bh = blockIdx.y;
    const int qt = (int)gridDim.x - 1 - (int)blockIdx.x;
    const int qbase = qt * 128;
    const int nkt = 2 * qt + 2;

    const int tid = threadIdx.x;
    const int lane = tid & 31;
    const int wid = tid >> 5;
    const int wr = wid * 16;

    const size_t hoff = (size_t)bh * SEQ * HD;
    const bf16* qsrc[2] = {Qhi_g + hoff, Qlo_g + hoff};
    const bf16* kvsrc[4] = {Khi_g + hoff, Klo_g + hoff, Vhi_g + hoff, Vlo_g + hoff};

    // stage Q into ring[0] (hi rows 0..127, lo rows 128..255)
#pragma unroll
    for (int i = 0; i < 8; i++) {
        int c = i * 256 + tid;
        int row = (c >> 3) & 127;
        int ch = (c & 7) * 8;
        cp16(sb + (uint32_t)(((i >> 2) * 128 + row) * STR + ch) * 2,
             qsrc[i >> 2] + (size_t)(qbase + row) * HD + ch);
    }
    asm volatile("cp.async.commit_group;");
    cp_wait<0>();
    __syncthreads();

    uint32_t qh[4][4], ql[4][4];
    {
        int arow = wr + (lane & 15);
        int acol = (lane >> 4) * 8;
#pragma unroll
        for (int ks = 0; ks < 4; ks++) {
            ldsm4(qh[ks][0], qh[ks][1], qh[ks][2], qh[ks][3],
                  sb + (uint32_t)(arow * STR + ks * 16 + acol) * 2);
            ldsm4(ql[ks][0], ql[ks][1], ql[ks][2], ql[ks][3],
                  sb + (uint32_t)((128 + arow) * STR + ks * 16 + acol) * 2);
        }
    }
    __syncthreads();   // Q reads done; ring[0] becomes KV stage

    float o[8][4];
#pragma unroll
    for (int i = 0; i < 8; i++)
#pragma unroll
        for (int j = 0; j < 4; j++) o[i][j] = 0.f;
    float m0 = -1e30f, m1 = -1e30f, l0 = 0.f, l1 = 0.f;

    kv_issue(sb, 0, 0, kvsrc, tid);
    kv_issue(sb, 1, 64, kvsrc, tid);

    const int brow = (lane & 7) + ((lane >> 4) << 3);
    const int bcol = ((lane >> 3) & 1) * 8;
    const int vrow = (lane & 7) + (((lane >> 3) & 1) << 3);
    const int vcol = (lane >> 4) * 8;

    int st = 0;
    for (int kt = 0; kt < nkt; kt++) {
        if (kt + 1 < nkt) cp_wait<1>(); else cp_wait<0>();
        __syncthreads();
        if (kt + 2 < nkt) {
            int b2 = st + 2; if (b2 >= 3) b2 -= 3;
            kv_issue(sb, b2, (kt + 2) * 64, kvsrc, tid);
        }

        const uint32_t kvb = sb + (uint32_t)st * KV_STAGE_B;
        const uint32_t Khi_s = kvb;
        const uint32_t Klo_s = kvb + 64 * STR * 2;
        const uint32_t Vhi_s = kvb + 128 * STR * 2;
        const uint32_t Vlo_s = kvb + 192 * STR * 2;
        const int kbase = kt * 64;

        // ---- S = Q K^T (3-pass split) ----
        float s[8][4];
#pragma unroll
        for (int i = 0; i < 8; i++)
#pragma unroll
            for (int j = 0; j < 4; j++) s[i][j] = 0.f;

#pragma unroll
        for (int ks = 0; ks < 4; ks++) {
            uint32_t bb[4][4];
#pragma unroll
            for (int ng = 0; ng < 4; ng++)
                ldsm4(bb[ng][0], bb[ng][1], bb[ng][2], bb[ng][3],
                      Khi_s + (uint32_t)((16 * ng + brow) * STR + 16 * ks + bcol) * 2);
#pragma unroll
            for (int ng = 0; ng < 4; ng++) {
                mma16816(s[2 * ng], qh[ks], bb[ng][0], bb[ng][1]);
                mma16816(s[2 * ng + 1], qh[ks], bb[ng][2], bb[ng][3]);
                mma16816(s[2 * ng], ql[ks], bb[ng][0], bb[ng][1]);
                mma16816(s[2 * ng + 1], ql[ks], bb[ng][2], bb[ng][3]);
            }
#pragma unroll
            for (int ng = 0; ng < 4; ng++)
                ldsm4(bb[ng][0], bb[ng][1], bb[ng][2], bb[ng][3],
                      Klo_s + (uint32_t)((16 * ng + brow) * STR + 16 * ks + bcol) * 2);
#pragma unroll
            for (int ng = 0; ng < 4; ng++) {
                mma16816(s[2 * ng], qh[ks], bb[ng][0], bb[ng][1]);
                mma16816(s[2 * ng + 1], qh[ks], bb[ng][2], bb[ng][3]);
            }
        }

        if (kbase + 63 > qbase + wr) {
            int row0 = qbase + wr + (lane >> 2);
            int colb = kbase + 2 * (lane & 3);
#pragma unroll
            for (int nt = 0; nt < 8; nt++) {
                int c0 = colb + nt * 8;
                if (c0 > row0) s[nt][0] = -1e30f;
                if (c0 + 1 > row0) s[nt][1] = -1e30f;
                if (c0 > row0 + 8) s[nt][2] = -1e30f;
                if (c0 + 1 > row0 + 8) s[nt][3] = -1e30f;
            }
        }

        // ---- online softmax (log2 domain) ----
        float mx0 = s[0][0], mx1 = s[0][2];
#pragma unroll
        for (int nt = 0; nt < 8; nt++) {
            mx0 = fmaxf(mx0, fmaxf(s[nt][0], s[nt][1]));
            mx1 = fmaxf(mx1, fmaxf(s[nt][2], s[nt][3]));
        }
        mx0 = fmaxf(mx0, __shfl_xor_sync(0xffffffffu, mx0, 1));
        mx0 = fmaxf(mx0, __shfl_xor_sync(0xffffffffu, mx0, 2));
        mx1 = fmaxf(mx1, __shfl_xor_sync(0xffffffffu, mx1, 1));
        mx1 = fmaxf(mx1, __shfl_xor_sync(0xffffffffu, mx1, 2));
        float mn0 = fmaxf(m0, mx0), mn1 = fmaxf(m1, mx1);
        float corr0 = ex2f(m0 - mn0), corr1 = ex2f(m1 - mn1);
        m0 = mn0; m1 = mn1;
        float rs0 = 0.f, rs1 = 0.f;
#pragma unroll
        for (int nt = 0; nt < 8; nt++) {
            s[nt][0] = ex2f(s[nt][0] - mn0); rs0 += s[nt][0];
            s[nt][1] = ex2f(s[nt][1] - mn0); rs0 += s[nt][1];
            s[nt][2] = ex2f(s[nt][2] - mn1); rs1 += s[nt][2];
            s[nt][3] = ex2f(s[nt][3] - mn1); rs1 += s[nt][3];
        }
        rs0 += __shfl_xor_sync(0xffffffffu, rs0, 1);
        rs0 += __shfl_xor_sync(0xffffffffu, rs0, 2);
        rs1 += __shfl_xor_sync(0xffffffffu, rs1, 1);
        rs1 += __shfl_xor_sync(0xffffffffu, rs1, 2);
        l0 = l0 * corr0 + rs0;
        l1 = l1 * corr1 + rs1;
#pragma unroll
        for (int nd = 0; nd < 8; nd++) {
            o[nd][0] *= corr0; o[nd][1] *= corr0;
            o[nd][2] *= corr1; o[nd][3] *= corr1;
        }

        // ---- P -> bf16 hi/lo A-fragments ----
        uint32_t phi[4][4], plo[4][4];
#pragma unroll
        for (int t = 0; t < 4; t++) {
#pragma unroll
            for (int half = 0; half < 2; half++) {
                const float* sp = s[2 * t + half];
                int i0 = half * 2, i1 = half * 2 + 1;
                uint32_t h0 = cvt_bf2(sp[0], sp[1]);
                phi[t][i0] = h0;
                plo[t][i0] = cvt_bf2(sp[0] - bflo(h0), sp[1] - bfhi(h0));
                uint32_t h1 = cvt_bf2(sp[2], sp[3]);
                phi[t][i1] = h1;
                plo[t][i1] = cvt_bf2(sp[2] - bflo(h1), sp[3] - bfhi(h1));
            }
        }

        // ---- O += P V (3-pass split, V via ldmatrix.trans) ----
#pragma unroll
        for (int t = 0; t < 4; t++) {
            uint32_t vb[4][4];
#pragma unroll
            for (int g = 0; g < 4; g++)
                ldsm4t(vb[g][0], vb[g][1], vb[g][2], vb[g][3],
                       Vhi_s + (uint32_t)((16 * t + vrow) * STR + 16 * g + vcol) * 2);
#pragma unroll
            for (int g = 0; g < 4; g++) {
                mma16816(o[2 * g], phi[t], vb[g][0], vb[g][1]);
                mma16816(o[2 * g + 1], phi[t], vb[g][2], vb[g][3]);
                mma16816(o[2 * g], plo[t], vb[g][0], vb[g][1]);
                mma16816(o[2 * g + 1], plo[t], vb[g][2], vb[g][3]);
            }
#pragma unroll
            for (int g = 0; g < 4; g++)
                ldsm4t(vb[g][0], vb[g][1], vb[g][2], vb[g][3],
                       Vlo_s + (uint32_t)((16 * t + vrow) * STR + 16 * g + vcol) * 2);
#pragma unroll
            for (int g = 0; g < 4; g++) {
                mma16816(o[2 * g], phi[t], vb[g][0], vb[g][1]);
                mma16816(o[2 * g + 1], phi[t], vb[g][2], vb[g][3]);
            }
        }

        st = (st + 1 == 3) ? 0 : st + 1;
    }

    // ---- epilogue: write ao pre-split hi/lo, [b][n][emb] ----
    float inv0 = 1.f / l0, inv1 = 1.f / l1;
    int b = bh / NH, h = bh % NH;
    int row0 = qbase + wr + (lane >> 2);
    size_t off0 = ((size_t)b * SEQ + row0) * EMB + h * HD + 2 * (lane & 3);
    size_t off1 = off0 + 8 * (size_t)EMB;
#pragma unroll
    for (int nd = 0; nd < 8; nd++) {
        float f0 = o[nd][0] * inv0, f1 = o[nd][1] * inv0;
        uint32_t hp = cvt_bf2(f0, f1);
        uint32_t lp = cvt_bf2(f0 - bflo(hp), f1 - bfhi(hp));
        *(uint32_t*)&AOhi[off0 + nd * 8] = hp;
        *(uint32_t*)&AOlo[off0 + nd * 8] = lp;
        float g0 = o[nd][2] * inv1, g1 = o[nd][3] * inv1;
        uint32_t hq = cvt_bf2(g0, g1);
        uint32_t lq = cvt_bf2(g0 - bflo(hq), g1 - bfhi(hq));
        *(uint32_t*)&AOhi[off1 + nd * 8] = hq;
        *(uint32_t*)&AOlo[off1 + nd * 8] = lq;
    }
}

// =================================================================
// launch
// =================================================================
extern "C" void kernel_launch(void* const* d_in, const int* in_sizes, int n_in,
                              void* d_out, int out_size)
{
    const float* x    = (const float*)d_in[0];
    const float* wq_b = (const float*)d_in[2];
    const float* wk_b = (const float*)d_in[4];
    const float* wv_b = (const float*)d_in[6];
    const float* wo_b = (const float*)d_in[8];
    float* out = (float*)d_out;

    bf16 *xhi, *xlo;
    bf16 *qhi, *qlo, *khi, *klo, *vhi, *vlo, *aohi, *aolo;
    cudaGetSymbolAddress((void**)&xhi, g_xhi);
    cudaGetSymbolAddress((void**)&xlo, g_xlo);
    cudaGetSymbolAddress((void**)&qhi, g_qhi);
    cudaGetSymbolAddress((void**)&qlo, g_qlo);
    cudaGetSymbolAddress((void**)&khi, g_khi);
    cudaGetSymbolAddress((void**)&klo, g_klo);
    cudaGetSymbolAddress((void**)&vhi, g_vhi);
    cudaGetSymbolAddress((void**)&vlo, g_vlo);
    cudaGetSymbolAddress((void**)&aohi, g_aohi);
    cudaGetSymbolAddress((void**)&aolo, g_aolo);

    cudaFuncSetAttribute(attn_mma,
                         cudaFuncAttributeMaxDynamicSharedMemorySize, ATT_SMEM);
    cudaFuncSetAttribute(qkv_mma,
                         cudaFuncAttributeMaxDynamicSharedMemorySize, GEMM_SMEM);
    cudaFuncSetAttribute(out_mma,
                         cudaFuncAttributeMaxDynamicSharedMemorySize, GEMM_SMEM);

    const int nx4 = MROWS * EMB / 4;
    split4_kernel<<<(nx4 + 255) / 256, 256>>>((const float4*)x,
                                              (uint2*)xhi, (uint2*)xlo, nx4);
    dim3 gw((EMB * EMB / 4 + 255) / 256, 1, 4);
    split_w4_kernel<<<gw, 256>>>((const float*)d_in[1], (const float*)d_in[3],
                                 (const float*)d_in[5], (const float*)d_in[7]);

    dim3 gqkv(NQKV / BN, MROWS / BM);              // 18 x 32 = 576
    qkv_mma<<<gqkv, 256, GEMM_SMEM>>>(wq_b, wk_b, wv_b);

    dim3 ga(SEQ / 128, BATCH * NH);                // 16 x 24
    attn_mma<<<ga, 256, ATT_SMEM>>>(qhi, qlo, khi, klo, vhi, vlo, aohi, aolo);

    dim3 go(EMB / BN, MROWS / BM);                 // 6 x 32
    out_mma<<<go, 256, GEMM_SMEM>>>(wo_b, out);
}